// round 6
// baseline (speedup 1.0000x reference)
#include <cuda_runtime.h>
#include <cstdint>

#define B_  2
#define S_  2048
#define D_  1024
#define H_  16
#define HD_ 64
#define SCALE_ 0.125f

// Scratch
__device__ float g_q[(size_t)B_ * H_ * S_ * HD_];
__device__ float g_k[(size_t)B_ * H_ * S_ * HD_];
__device__ float g_v[(size_t)B_ * H_ * S_ * HD_];
__device__ float g_att[(size_t)B_ * S_ * D_];
__device__ float g_wqkvt[(size_t)3 * D_ * D_];   // Wqkv^T  [3072,1024]
__device__ float g_wprojt[(size_t)D_ * D_];      // Wproj^T [1024,1024]

__device__ __forceinline__ uint32_t f2tf32(float x) {
    uint32_t u;
    asm("cvt.rna.tf32.f32 %0, %1;" : "=r"(u) : "f"(x));
    return u;
}

// D = A(16x8 tf32 row) * B(8x8 tf32 col) + D, fp32 accum
__device__ __forceinline__ void mma8(float d[4], const uint32_t a[4], uint32_t b0, uint32_t b1) {
    asm volatile(
        "mma.sync.aligned.m16n8k8.row.col.f32.tf32.tf32.f32 "
        "{%0,%1,%2,%3},{%4,%5,%6,%7},{%8,%9},{%0,%1,%2,%3};"
        : "+f"(d[0]), "+f"(d[1]), "+f"(d[2]), "+f"(d[3])
        : "r"(a[0]), "r"(a[1]), "r"(a[2]), "r"(a[3]), "r"(b0), "r"(b1));
}

// Column permutation within each 8-group: pairs (c, c+4) -> (2c, 2c+1)
__device__ __forceinline__ int sigma8(int d) {
    return (d & ~7) | ((d & 3) << 1) | ((d >> 2) & 1);
}

// ---------------------------------------------------------------------------
// Transpose: out[C,R] = in[R,C]
// ---------------------------------------------------------------------------
__global__ __launch_bounds__(256) void transpose_kernel(const float* __restrict__ in,
                                                        float* __restrict__ out,
                                                        int R, int C) {
    __shared__ float t[32][33];
    const int bx = blockIdx.x * 32, by = blockIdx.y * 32;
    for (int i = threadIdx.y; i < 32; i += 8)
        t[i][threadIdx.x] = in[(size_t)(by + i) * C + bx + threadIdx.x];
    __syncthreads();
    for (int i = threadIdx.y; i < 32; i += 8)
        out[(size_t)(bx + i) * R + by + threadIdx.x] = t[threadIdx.x][i];
}

// ---------------------------------------------------------------------------
// mma.sync tf32 GEMM: C[M,N] = A[M,1024] @ Bt[N,1024]^T + bias
// 128x128 CTA tile, 256 thr (8 warps 2x4), warp tile 64x32, BK=32.
// k-columns stored sigma-permuted; stride 40 words -> conflict-free LDS.64.
// ---------------------------------------------------------------------------
template <int NTOT, int MODE>
__global__ __launch_bounds__(256) void mma_gemm(const float* __restrict__ A,
                                                const float* __restrict__ Bt,
                                                const float* __restrict__ bias,
                                                float* __restrict__ Cout) {
    constexpr int K = 1024;
    constexpr int ST = 40;
    __shared__ uint32_t As[128 * ST];
    __shared__ uint32_t Bs[128 * ST];

    const int tid = threadIdx.x, lane = tid & 31, w = tid >> 5;
    const int bm = blockIdx.y * 128, bn = blockIdx.x * 128;
    const int wm = (w & 1) * 64, wn = (w >> 1) * 32;
    const int r = lane >> 2, c = lane & 3;

    float acc[4][4][4];
#pragma unroll
    for (int mi = 0; mi < 4; mi++)
#pragma unroll
        for (int ni = 0; ni < 4; ni++)
#pragma unroll
            for (int q = 0; q < 4; q++) acc[mi][ni][q] = 0.0f;

    for (int k0 = 0; k0 < K; k0 += 32) {
#pragma unroll
        for (int it = 0; it < 4; it++) {
            const int slot = tid + it * 256;
            const int row = slot >> 3, c4 = (slot & 7) * 4;
            const int base = (c4 & ~7) + ((c4 >> 2) & 1);   // sigma of c4..c4+3 => base+2j
            float4 va = *reinterpret_cast<const float4*>(A + (size_t)(bm + row) * K + k0 + c4);
            uint32_t* ad = As + row * ST + base;
            ad[0] = f2tf32(va.x); ad[2] = f2tf32(va.y); ad[4] = f2tf32(va.z); ad[6] = f2tf32(va.w);
            float4 vb = *reinterpret_cast<const float4*>(Bt + (size_t)(bn + row) * K + k0 + c4);
            uint32_t* bd = Bs + row * ST + base;
            bd[0] = f2tf32(vb.x); bd[2] = f2tf32(vb.y); bd[4] = f2tf32(vb.z); bd[6] = f2tf32(vb.w);
        }
        __syncthreads();

#pragma unroll
        for (int ks = 0; ks < 4; ks++) {
            const int k2 = ks * 8 + 2 * c;
            uint32_t af[4][4];
#pragma unroll
            for (int mi = 0; mi < 4; mi++) {
                uint2 a01 = *reinterpret_cast<const uint2*>(As + (wm + mi * 16 + r) * ST + k2);
                uint2 a23 = *reinterpret_cast<const uint2*>(As + (wm + mi * 16 + 8 + r) * ST + k2);
                af[mi][0] = a01.x; af[mi][1] = a23.x; af[mi][2] = a01.y; af[mi][3] = a23.y;
            }
            uint2 bf[4];
#pragma unroll
            for (int ni = 0; ni < 4; ni++)
                bf[ni] = *reinterpret_cast<const uint2*>(Bs + (wn + ni * 8 + r) * ST + k2);
#pragma unroll
            for (int mi = 0; mi < 4; mi++)
#pragma unroll
                for (int ni = 0; ni < 4; ni++)
                    mma8(acc[mi][ni], af[mi], bf[ni].x, bf[ni].y);
        }
        __syncthreads();
    }

    // Epilogue
    const int c2 = (lane & 3) * 2;
#pragma unroll
    for (int mi = 0; mi < 4; mi++) {
#pragma unroll
        for (int ni = 0; ni < 4; ni++) {
            const int col = bn + wn + ni * 8 + c2;
            const float bi0 = bias[col], bi1 = bias[col + 1];
#pragma unroll
            for (int half = 0; half < 2; half++) {
                const int row = bm + wm + mi * 16 + r + half * 8;
                const float v0 = acc[mi][ni][half * 2 + 0] + bi0;
                const float v1 = acc[mi][ni][half * 2 + 1] + bi1;
                if (MODE == 0) {
                    const int which = col >> 10;
                    const int d     = col & 1023;
                    const int h     = d >> 6;
                    const int hd    = d & 63;
                    const int b     = row >> 11;
                    const int s     = row & 2047;
                    const size_t dst = (((size_t)b * H_ + h) * S_ + s) * HD_ + hd;
                    float2 v = {v0, v1};
                    if (which == 0)      *reinterpret_cast<float2*>(g_q + dst) = v;
                    else if (which == 1) *reinterpret_cast<float2*>(g_k + dst) = v;
                    else                 *reinterpret_cast<float2*>(g_v + dst) = v;
                } else {
                    float2 v = {v0, v1};
                    *reinterpret_cast<float2*>(Cout + (size_t)row * NTOT + col) = v;
                }
            }
        }
    }
}

// ---------------------------------------------------------------------------
// Flash attention, mma.sync tf32, register softmax, sigma-permuted tiles.
// CTA: 256 thr (8 warps), Br=128, Bc=64, HD=64. Stride 72 words.
// SMEM: Qs[128][72] Ks[64][72] Vs[64][72] Ss[128][72] = 110,592 B.
// ---------------------------------------------------------------------------
__global__ __launch_bounds__(256) void attn_mma() {
    constexpr int ST = 72;
    extern __shared__ uint32_t smu[];
    uint32_t* Qs = smu;                    // [128][72]  cols sigma-permuted (d)
    uint32_t* Ks = Qs + 128 * ST;          // [64][72]   cols sigma-permuted (d)
    uint32_t* Vs = Ks + 64 * ST;           // [64][72]   row=d, col=sigma(k-idx)
    uint32_t* Ss = Vs + 64 * ST;           // [128][72]  cols sigma-permuted (k)

    const int b  = blockIdx.z;
    const int h  = blockIdx.y;
    const int q0 = blockIdx.x * 128;

    const size_t head_off = ((size_t)b * H_ + h) * S_ * HD_;
    const float* Qg = g_q + head_off;
    const float* Kg = g_k + head_off;
    const float* Vg = g_v + head_off;

    const int tid = threadIdx.x, lane = tid & 31, w = tid >> 5;
    const int wrow = w * 16;
    const int r = lane >> 2, c = lane & 3;
    const int c2 = c * 2;
    // sigma position of accumulator column pair (2c, 2c+1): s0, s0+2
    const int s0 = (c & 1) * 4 + (c >> 1);

    // Load Q tile (128x64), sigma-permuted cols
#pragma unroll
    for (int it = 0; it < 8; it++) {
        const int slot = tid + it * 256;
        const int row = slot >> 4, c4 = (slot & 15) * 4;
        const int base = (c4 & ~7) + ((c4 >> 2) & 1);
        float4 v = *reinterpret_cast<const float4*>(Qg + (size_t)(q0 + row) * HD_ + c4);
        uint32_t* d = Qs + row * ST + base;
        d[0] = f2tf32(v.x); d[2] = f2tf32(v.y); d[4] = f2tf32(v.z); d[6] = f2tf32(v.w);
    }

    float m0 = -1e30f, m1 = -1e30f, l0 = 0.0f, l1 = 0.0f;
    float O[8][4];
#pragma unroll
    for (int ni = 0; ni < 8; ni++)
#pragma unroll
        for (int q = 0; q < 4; q++) O[ni][q] = 0.0f;

    for (int kt = 0; kt < S_; kt += 64) {
        __syncthreads();
#pragma unroll
        for (int it = 0; it < 4; it++) {
            const int slot = tid + it * 256;
            const int row = slot >> 4, c4 = (slot & 15) * 4;
            const int base = (c4 & ~7) + ((c4 >> 2) & 1);
            float4 kv = *reinterpret_cast<const float4*>(Kg + (size_t)(kt + row) * HD_ + c4);
            uint32_t* kd = Ks + row * ST + base;
            kd[0] = f2tf32(kv.x); kd[2] = f2tf32(kv.y); kd[4] = f2tf32(kv.z); kd[6] = f2tf32(kv.w);
            float4 vv = *reinterpret_cast<const float4*>(Vg + (size_t)(kt + row) * HD_ + c4);
            const int sp = sigma8(row);          // permuted k-index
            Vs[(c4 + 0) * ST + sp] = f2tf32(vv.x);
            Vs[(c4 + 1) * ST + sp] = f2tf32(vv.y);
            Vs[(c4 + 2) * ST + sp] = f2tf32(vv.z);
            Vs[(c4 + 3) * ST + sp] = f2tf32(vv.w);
        }
        __syncthreads();

        // S = Q @ K^T
        float sf[8][4];
#pragma unroll
        for (int ni = 0; ni < 8; ni++)
#pragma unroll
            for (int q = 0; q < 4; q++) sf[ni][q] = 0.0f;
#pragma unroll
        for (int ks = 0; ks < 8; ks++) {
            const int k2 = ks * 8 + c2;
            uint2 a01 = *reinterpret_cast<const uint2*>(Qs + (wrow + r) * ST + k2);
            uint2 a23 = *reinterpret_cast<const uint2*>(Qs + (wrow + 8 + r) * ST + k2);
            uint32_t af[4] = {a01.x, a23.x, a01.y, a23.y};
#pragma unroll
            for (int ni = 0; ni < 8; ni++) {
                uint2 bb = *reinterpret_cast<const uint2*>(Ks + (ni * 8 + r) * ST + k2);
                mma8(sf[ni], af, bb.x, bb.y);
            }
        }

        // register softmax
        float mloc0 = -1e30f, mloc1 = -1e30f;
#pragma unroll
        for (int ni = 0; ni < 8; ni++) {
            sf[ni][0] *= SCALE_; sf[ni][1] *= SCALE_;
            sf[ni][2] *= SCALE_; sf[ni][3] *= SCALE_;
            mloc0 = fmaxf(mloc0, fmaxf(sf[ni][0], sf[ni][1]));
            mloc1 = fmaxf(mloc1, fmaxf(sf[ni][2], sf[ni][3]));
        }
        mloc0 = fmaxf(mloc0, __shfl_xor_sync(0xffffffffu, mloc0, 1));
        mloc0 = fmaxf(mloc0, __shfl_xor_sync(0xffffffffu, mloc0, 2));
        mloc1 = fmaxf(mloc1, __shfl_xor_sync(0xffffffffu, mloc1, 1));
        mloc1 = fmaxf(mloc1, __shfl_xor_sync(0xffffffffu, mloc1, 2));

        const float mnew0 = fmaxf(m0, mloc0);
        const float mnew1 = fmaxf(m1, mloc1);
        const float alpha0 = __expf(m0 - mnew0);
        const float alpha1 = __expf(m1 - mnew1);

        float ls0 = 0.0f, ls1 = 0.0f;
#pragma unroll
        for (int ni = 0; ni < 8; ni++) {
            const float p0 = __expf(sf[ni][0] - mnew0);
            const float p1 = __expf(sf[ni][1] - mnew0);
            const float p2 = __expf(sf[ni][2] - mnew1);
            const float p3 = __expf(sf[ni][3] - mnew1);
            ls0 += p0 + p1;
            ls1 += p2 + p3;
            uint32_t* pd0 = Ss + (wrow + r) * ST + ni * 8 + s0;
            pd0[0] = f2tf32(p0); pd0[2] = f2tf32(p1);
            uint32_t* pd1 = Ss + (wrow + 8 + r) * ST + ni * 8 + s0;
            pd1[0] = f2tf32(p2); pd1[2] = f2tf32(p3);
        }
        ls0 += __shfl_xor_sync(0xffffffffu, ls0, 1);
        ls0 += __shfl_xor_sync(0xffffffffu, ls0, 2);
        ls1 += __shfl_xor_sync(0xffffffffu, ls1, 1);
        ls1 += __shfl_xor_sync(0xffffffffu, ls1, 2);

        l0 = l0 * alpha0 + ls0;  m0 = mnew0;
        l1 = l1 * alpha1 + ls1;  m1 = mnew1;

#pragma unroll
        for (int ni = 0; ni < 8; ni++) {
            O[ni][0] *= alpha0; O[ni][1] *= alpha0;
            O[ni][2] *= alpha1; O[ni][3] *= alpha1;
        }
        __syncwarp();

        // O += P @ V
#pragma unroll
        for (int ks = 0; ks < 8; ks++) {
            const int k2 = ks * 8 + c2;
            uint2 a01 = *reinterpret_cast<const uint2*>(Ss + (wrow + r) * ST + k2);
            uint2 a23 = *reinterpret_cast<const uint2*>(Ss + (wrow + 8 + r) * ST + k2);
            uint32_t af[4] = {a01.x, a23.x, a01.y, a23.y};
#pragma unroll
            for (int ni = 0; ni < 8; ni++) {
                uint2 bb = *reinterpret_cast<const uint2*>(Vs + (ni * 8 + r) * ST + k2);
                mma8(O[ni], af, bb.x, bb.y);
            }
        }
    }

    // Normalize and write out
    const float il0 = 1.0f / l0;
    const float il1 = 1.0f / l1;
#pragma unroll
    for (int ni = 0; ni < 8; ni++) {
        const int col = h * HD_ + ni * 8 + c2;
        const int row0 = q0 + wrow + r;
        float2 v0 = {O[ni][0] * il0, O[ni][1] * il0};
        float2 v1 = {O[ni][2] * il1, O[ni][3] * il1};
        *reinterpret_cast<float2*>(g_att + ((size_t)b * S_ + row0) * D_ + col)     = v0;
        *reinterpret_cast<float2*>(g_att + ((size_t)b * S_ + row0 + 8) * D_ + col) = v1;
    }
}

// ---------------------------------------------------------------------------
extern "C" void kernel_launch(void* const* d_in, const int* in_sizes, int n_in,
                              void* d_out, int out_size) {
    (void)in_sizes; (void)n_in; (void)out_size;
    const float* x     = (const float*)d_in[0];
    const float* Wqkv  = (const float*)d_in[1];
    const float* bqkv  = (const float*)d_in[2];
    const float* Wproj = (const float*)d_in[3];
    const float* bproj = (const float*)d_in[4];
    float* out = (float*)d_out;

    float *att_dev = nullptr, *wqkvt_dev = nullptr, *wprojt_dev = nullptr;
    cudaGetSymbolAddress((void**)&att_dev,    g_att);
    cudaGetSymbolAddress((void**)&wqkvt_dev,  g_wqkvt);
    cudaGetSymbolAddress((void**)&wprojt_dev, g_wprojt);

    // Transpose weights to K-major [N,K]
    {
        dim3 blk(32, 8);
        transpose_kernel<<<dim3(3 * D_ / 32, D_ / 32), blk>>>(Wqkv, wqkvt_dev, D_, 3 * D_);
        transpose_kernel<<<dim3(D_ / 32, D_ / 32), blk>>>(Wproj, wprojt_dev, D_, D_);
    }

    // QKV GEMM
    {
        dim3 grid(3 * D_ / 128, (B_ * S_) / 128);
        mma_gemm<3 * D_, 0><<<grid, 256>>>(x, wqkvt_dev, bqkv, nullptr);
    }

    // Attention
    {
        const int smem = (128 + 64 + 64 + 128) * 72 * 4;  // 110,592
        cudaFuncSetAttribute(attn_mma, cudaFuncAttributeMaxDynamicSharedMemorySize, smem);
        dim3 grid(S_ / 128, H_, B_);
        attn_mma<<<grid, 256, smem>>>();
    }

    // Output projection
    {
        dim3 grid(D_ / 128, (B_ * S_) / 128);
        mma_gemm<D_, 1><<<grid, 256>>>(att_dev, wprojt_dev, bproj, out);
    }
}

// round 8
// speedup vs baseline: 1.3493x; 1.3493x over previous
#include <cuda_runtime.h>
#include <cstdint>

#define B_  2
#define S_  2048
#define D_  1024
#define H_  16
#define HD_ 64
#define SCALE_ 0.125f

// Scratch
__device__ float g_q[(size_t)B_ * H_ * S_ * HD_];
__device__ float g_k[(size_t)B_ * H_ * S_ * HD_];
__device__ float g_v[(size_t)B_ * H_ * S_ * HD_];
__device__ float g_att[(size_t)B_ * S_ * D_];
__device__ float g_wqkvt[(size_t)3 * D_ * D_];   // Wqkv^T  [3072,1024]
__device__ float g_wprojt[(size_t)D_ * D_];      // Wproj^T [1024,1024]

__device__ __forceinline__ uint32_t f2tf32(float x) {
    uint32_t u;
    asm("cvt.rna.tf32.f32 %0, %1;" : "=r"(u) : "f"(x));
    return u;
}

// D = A(16x8 tf32 row) * B(8x8 tf32 col) + D, fp32 accum
__device__ __forceinline__ void mma8(float d[4], const uint32_t a[4], uint32_t b0, uint32_t b1) {
    asm volatile(
        "mma.sync.aligned.m16n8k8.row.col.f32.tf32.tf32.f32 "
        "{%0,%1,%2,%3},{%4,%5,%6,%7},{%8,%9},{%0,%1,%2,%3};"
        : "+f"(d[0]), "+f"(d[1]), "+f"(d[2]), "+f"(d[3])
        : "r"(a[0]), "r"(a[1]), "r"(a[2]), "r"(a[3]), "r"(b0), "r"(b1));
}

// ---------------------------------------------------------------------------
// Transpose: out[C,R] = in[R,C]
// ---------------------------------------------------------------------------
__global__ __launch_bounds__(256) void transpose_kernel(const float* __restrict__ in,
                                                        float* __restrict__ out,
                                                        int R, int C) {
    __shared__ float t[32][33];
    const int bx = blockIdx.x * 32, by = blockIdx.y * 32;
    for (int i = threadIdx.y; i < 32; i += 8)
        t[i][threadIdx.x] = in[(size_t)(by + i) * C + bx + threadIdx.x];
    __syncthreads();
    for (int i = threadIdx.y; i < 32; i += 8)
        out[(size_t)(bx + i) * R + by + threadIdx.x] = t[threadIdx.x][i];
}

// ---------------------------------------------------------------------------
// mma.sync tf32 GEMM (R5 version, proven): C = A[M,1024] @ Bt[N,1024]^T + bias
// 128x128 CTA tile, 256 thr (8 warps 2x4), warp tile 64x32, BK=32.
// ---------------------------------------------------------------------------
template <int NTOT, int MODE>
__global__ __launch_bounds__(256) void mma_gemm(const float* __restrict__ A,
                                                const float* __restrict__ Bt,
                                                const float* __restrict__ bias,
                                                float* __restrict__ Cout) {
    constexpr int K = 1024;
    __shared__ uint32_t As[128][36];   // [m][k]
    __shared__ uint32_t Bs[128][36];   // [n][k]

    const int tid = threadIdx.x, lane = tid & 31, w = tid >> 5;
    const int bm = blockIdx.y * 128, bn = blockIdx.x * 128;
    const int wm = (w & 1) * 64, wn = (w >> 1) * 32;
    const int r = lane >> 2, c = lane & 3;

    float acc[4][4][4];
#pragma unroll
    for (int mi = 0; mi < 4; mi++)
#pragma unroll
        for (int ni = 0; ni < 4; ni++)
#pragma unroll
            for (int q = 0; q < 4; q++) acc[mi][ni][q] = 0.0f;

    for (int k0 = 0; k0 < K; k0 += 32) {
#pragma unroll
        for (int it = 0; it < 4; it++) {
            const int slot = tid + it * 256;
            const int row = slot >> 3, c4 = (slot & 7) * 4;
            float4 va = *reinterpret_cast<const float4*>(A + (size_t)(bm + row) * K + k0 + c4);
            As[row][c4 + 0] = f2tf32(va.x); As[row][c4 + 1] = f2tf32(va.y);
            As[row][c4 + 2] = f2tf32(va.z); As[row][c4 + 3] = f2tf32(va.w);
            float4 vb = *reinterpret_cast<const float4*>(Bt + (size_t)(bn + row) * K + k0 + c4);
            Bs[row][c4 + 0] = f2tf32(vb.x); Bs[row][c4 + 1] = f2tf32(vb.y);
            Bs[row][c4 + 2] = f2tf32(vb.z); Bs[row][c4 + 3] = f2tf32(vb.w);
        }
        __syncthreads();

#pragma unroll
        for (int ks = 0; ks < 4; ks++) {
            const int k = ks * 8;
            uint32_t af[4][4];
#pragma unroll
            for (int mi = 0; mi < 4; mi++) {
                af[mi][0] = As[wm + mi * 16 + r][k + c];
                af[mi][1] = As[wm + mi * 16 + 8 + r][k + c];
                af[mi][2] = As[wm + mi * 16 + r][k + c + 4];
                af[mi][3] = As[wm + mi * 16 + 8 + r][k + c + 4];
            }
            uint32_t bf[4][2];
#pragma unroll
            for (int ni = 0; ni < 4; ni++) {
                bf[ni][0] = Bs[wn + ni * 8 + r][k + c];
                bf[ni][1] = Bs[wn + ni * 8 + r][k + c + 4];
            }
#pragma unroll
            for (int mi = 0; mi < 4; mi++)
#pragma unroll
                for (int ni = 0; ni < 4; ni++)
                    mma8(acc[mi][ni], af[mi], bf[ni][0], bf[ni][1]);
        }
        __syncthreads();
    }

    // Epilogue
    const int c2 = (lane & 3) * 2;
#pragma unroll
    for (int mi = 0; mi < 4; mi++) {
#pragma unroll
        for (int ni = 0; ni < 4; ni++) {
            const int col = bn + wn + ni * 8 + c2;
            const float bi0 = bias[col], bi1 = bias[col + 1];
#pragma unroll
            for (int half = 0; half < 2; half++) {
                const int row = bm + wm + mi * 16 + r + half * 8;
                const float v0 = acc[mi][ni][half * 2 + 0] + bi0;
                const float v1 = acc[mi][ni][half * 2 + 1] + bi1;
                if (MODE == 0) {
                    const int which = col >> 10;
                    const int d     = col & 1023;
                    const int h     = d >> 6;
                    const int hd    = d & 63;
                    const int b     = row >> 11;
                    const int s     = row & 2047;
                    const size_t dst = (((size_t)b * H_ + h) * S_ + s) * HD_ + hd;
                    float2 v = {v0, v1};
                    if (which == 0)      *reinterpret_cast<float2*>(g_q + dst) = v;
                    else if (which == 1) *reinterpret_cast<float2*>(g_k + dst) = v;
                    else                 *reinterpret_cast<float2*>(g_v + dst) = v;
                } else {
                    float2 v = {v0, v1};
                    *reinterpret_cast<float2*>(Cout + (size_t)row * NTOT + col) = v;
                }
            }
        }
    }
}

// ---------------------------------------------------------------------------
// Flash attention, mma.sync tf32, register softmax.
// CTA: 128 thr (4 warps). Br=128, Bc=64, HD=64.
// Warp w owns q-rows [w*32, w*32+32) (mi=0,1 row-groups of 16).
// K/V tile for the NEXT iteration is prefetched into registers during compute.
// SMEM: Qs[128][68] Ks[64][68] Vs[64][68] Ss[128][68] = 104,448 B.
// ---------------------------------------------------------------------------
__global__ __launch_bounds__(128, 2) void attn_mma() {
    constexpr int ST = 68;
    extern __shared__ uint32_t smu[];
    uint32_t* Qs = smu;                    // [128][68]
    uint32_t* Ks = Qs + 128 * ST;          // [64][68]
    uint32_t* Vs = Ks + 64 * ST;           // [64][68]  (row=d, col=k)
    uint32_t* Ss = Vs + 64 * ST;           // [128][68] (tf32 P, warp-private rows)

    const int b  = blockIdx.z;
    const int h  = blockIdx.y;
    const int q0 = blockIdx.x * 128;

    const size_t head_off = ((size_t)b * H_ + h) * S_ * HD_;
    const float* Qg = g_q + head_off;
    const float* Kg = g_k + head_off;
    const float* Vg = g_v + head_off;

    const int tid = threadIdx.x, lane = tid & 31, w = tid >> 5;
    const int wrow = w * 32;
    const int r = lane >> 2, c = lane & 3;
    const int c2 = c * 2;

    // Load Q tile (128x64), tf32
#pragma unroll
    for (int it = 0; it < 16; it++) {
        const int slot = tid + it * 128;
        const int row = slot >> 4, c4 = (slot & 15) * 4;
        float4 v = *reinterpret_cast<const float4*>(Qg + (size_t)(q0 + row) * HD_ + c4);
        uint32_t* d = Qs + row * ST + c4;
        d[0] = f2tf32(v.x); d[1] = f2tf32(v.y); d[2] = f2tf32(v.z); d[3] = f2tf32(v.w);
    }

    // Per-thread K/V tile slots (8 iterations each)
    const int ldrow = tid >> 4;            // slot row for it=0 (rows advance by 8/iter)
    const int ldc4  = (tid & 15) * 4;

    // Prefetch tile 0 into registers
    float4 kreg[8], vreg[8];
#pragma unroll
    for (int it = 0; it < 8; it++) {
        const int row = ldrow + it * 8;
        kreg[it] = *reinterpret_cast<const float4*>(Kg + (size_t)row * HD_ + ldc4);
        vreg[it] = *reinterpret_cast<const float4*>(Vg + (size_t)row * HD_ + ldc4);
    }

    float m[4], l[4];
#pragma unroll
    for (int i = 0; i < 4; i++) { m[i] = -1e30f; l[i] = 0.0f; }
    float O[2][8][4];
#pragma unroll
    for (int mi = 0; mi < 2; mi++)
#pragma unroll
        for (int ni = 0; ni < 8; ni++)
#pragma unroll
            for (int q = 0; q < 4; q++) O[mi][ni][q] = 0.0f;

    for (int kt = 0; kt < S_; kt += 64) {
        __syncthreads();   // prev tile's Ks/Vs consumers done
        // Store prefetched tile to SMEM (cvt to tf32)
#pragma unroll
        for (int it = 0; it < 8; it++) {
            const int row = ldrow + it * 8;
            uint32_t* kd = Ks + row * ST + ldc4;
            kd[0] = f2tf32(kreg[it].x); kd[1] = f2tf32(kreg[it].y);
            kd[2] = f2tf32(kreg[it].z); kd[3] = f2tf32(kreg[it].w);
            Vs[(ldc4 + 0) * ST + row] = f2tf32(vreg[it].x);
            Vs[(ldc4 + 1) * ST + row] = f2tf32(vreg[it].y);
            Vs[(ldc4 + 2) * ST + row] = f2tf32(vreg[it].z);
            Vs[(ldc4 + 3) * ST + row] = f2tf32(vreg[it].w);
        }
        __syncthreads();

        // Prefetch next tile (overlaps with compute below)
        if (kt + 64 < S_) {
            const float* Kn = Kg + (size_t)(kt + 64) * HD_;
            const float* Vn = Vg + (size_t)(kt + 64) * HD_;
#pragma unroll
            for (int it = 0; it < 8; it++) {
                const int row = ldrow + it * 8;
                kreg[it] = *reinterpret_cast<const float4*>(Kn + (size_t)row * HD_ + ldc4);
                vreg[it] = *reinterpret_cast<const float4*>(Vn + (size_t)row * HD_ + ldc4);
            }
        }

        // S = Q @ K^T : warp computes 32 rows x 64 cols
        float sf[2][8][4];
#pragma unroll
        for (int mi = 0; mi < 2; mi++)
#pragma unroll
            for (int ni = 0; ni < 8; ni++)
#pragma unroll
                for (int q = 0; q < 4; q++) sf[mi][ni][q] = 0.0f;
#pragma unroll
        for (int ks = 0; ks < 8; ks++) {
            const int k = ks * 8;
            uint32_t af[2][4];
#pragma unroll
            for (int mi = 0; mi < 2; mi++) {
                af[mi][0] = Qs[(wrow + mi * 16 + r) * ST + k + c];
                af[mi][1] = Qs[(wrow + mi * 16 + 8 + r) * ST + k + c];
                af[mi][2] = Qs[(wrow + mi * 16 + r) * ST + k + c + 4];
                af[mi][3] = Qs[(wrow + mi * 16 + 8 + r) * ST + k + c + 4];
            }
#pragma unroll
            for (int ni = 0; ni < 8; ni++) {
                const uint32_t b0 = Ks[(ni * 8 + r) * ST + k + c];
                const uint32_t b1 = Ks[(ni * 8 + r) * ST + k + c + 4];
                mma8(sf[0][ni], af[0], b0, b1);
                mma8(sf[1][ni], af[1], b0, b1);
            }
        }

        // register softmax (per mi group of 16 rows)
#pragma unroll
        for (int mi = 0; mi < 2; mi++) {
            float mloc0 = -1e30f, mloc1 = -1e30f;
#pragma unroll
            for (int ni = 0; ni < 8; ni++) {
                sf[mi][ni][0] *= SCALE_; sf[mi][ni][1] *= SCALE_;
                sf[mi][ni][2] *= SCALE_; sf[mi][ni][3] *= SCALE_;
                mloc0 = fmaxf(mloc0, fmaxf(sf[mi][ni][0], sf[mi][ni][1]));
                mloc1 = fmaxf(mloc1, fmaxf(sf[mi][ni][2], sf[mi][ni][3]));
            }
            mloc0 = fmaxf(mloc0, __shfl_xor_sync(0xffffffffu, mloc0, 1));
            mloc0 = fmaxf(mloc0, __shfl_xor_sync(0xffffffffu, mloc0, 2));
            mloc1 = fmaxf(mloc1, __shfl_xor_sync(0xffffffffu, mloc1, 1));
            mloc1 = fmaxf(mloc1, __shfl_xor_sync(0xffffffffu, mloc1, 2));

            const float mnew0 = fmaxf(m[mi * 2 + 0], mloc0);
            const float mnew1 = fmaxf(m[mi * 2 + 1], mloc1);
            const float alpha0 = __expf(m[mi * 2 + 0] - mnew0);
            const float alpha1 = __expf(m[mi * 2 + 1] - mnew1);

            float ls0 = 0.0f, ls1 = 0.0f;
#pragma unroll
            for (int ni = 0; ni < 8; ni++) {
                const float p0 = __expf(sf[mi][ni][0] - mnew0);
                const float p1 = __expf(sf[mi][ni][1] - mnew0);
                const float p2 = __expf(sf[mi][ni][2] - mnew1);
                const float p3 = __expf(sf[mi][ni][3] - mnew1);
                ls0 += p0 + p1;
                ls1 += p2 + p3;
                uint2 u0 = {f2tf32(p0), f2tf32(p1)};
                uint2 u1 = {f2tf32(p2), f2tf32(p3)};
                *reinterpret_cast<uint2*>(Ss + (wrow + mi * 16 + r) * ST + ni * 8 + c2)     = u0;
                *reinterpret_cast<uint2*>(Ss + (wrow + mi * 16 + 8 + r) * ST + ni * 8 + c2) = u1;
            }
            ls0 += __shfl_xor_sync(0xffffffffu, ls0, 1);
            ls0 += __shfl_xor_sync(0xffffffffu, ls0, 2);
            ls1 += __shfl_xor_sync(0xffffffffu, ls1, 1);
            ls1 += __shfl_xor_sync(0xffffffffu, ls1, 2);

            l[mi * 2 + 0] = l[mi * 2 + 0] * alpha0 + ls0;  m[mi * 2 + 0] = mnew0;
            l[mi * 2 + 1] = l[mi * 2 + 1] * alpha1 + ls1;  m[mi * 2 + 1] = mnew1;

#pragma unroll
            for (int ni = 0; ni < 8; ni++) {
                O[mi][ni][0] *= alpha0; O[mi][ni][1] *= alpha0;
                O[mi][ni][2] *= alpha1; O[mi][ni][3] *= alpha1;
            }
        }
        __syncwarp();   // P visible within warp

        // O += P @ V
#pragma unroll
        for (int ks = 0; ks < 8; ks++) {
            const int k = ks * 8;
            uint32_t af[2][4];
#pragma unroll
            for (int mi = 0; mi < 2; mi++) {
                af[mi][0] = Ss[(wrow + mi * 16 + r) * ST + k + c];
                af[mi][1] = Ss[(wrow + mi * 16 + 8 + r) * ST + k + c];
                af[mi][2] = Ss[(wrow + mi * 16 + r) * ST + k + c + 4];
                af[mi][3] = Ss[(wrow + mi * 16 + 8 + r) * ST + k + c + 4];
            }
#pragma unroll
            for (int ni = 0; ni < 8; ni++) {
                const uint32_t b0 = Vs[(ni * 8 + r) * ST + k + c];
                const uint32_t b1 = Vs[(ni * 8 + r) * ST + k + c + 4];
                mma8(O[0][ni], af[0], b0, b1);
                mma8(O[1][ni], af[1], b0, b1);
            }
        }
    }

    // Normalize and write out
#pragma unroll
    for (int mi = 0; mi < 2; mi++) {
        const float il0 = 1.0f / l[mi * 2 + 0];
        const float il1 = 1.0f / l[mi * 2 + 1];
#pragma unroll
        for (int ni = 0; ni < 8; ni++) {
            const int col = h * HD_ + ni * 8 + c2;
            const int row0 = q0 + wrow + mi * 16 + r;
            float2 v0 = {O[mi][ni][0] * il0, O[mi][ni][1] * il0};
            float2 v1 = {O[mi][ni][2] * il1, O[mi][ni][3] * il1};
            *reinterpret_cast<float2*>(g_att + ((size_t)b * S_ + row0) * D_ + col)     = v0;
            *reinterpret_cast<float2*>(g_att + ((size_t)b * S_ + row0 + 8) * D_ + col) = v1;
        }
    }
}

// ---------------------------------------------------------------------------
extern "C" void kernel_launch(void* const* d_in, const int* in_sizes, int n_in,
                              void* d_out, int out_size) {
    (void)in_sizes; (void)n_in; (void)out_size;
    const float* x     = (const float*)d_in[0];
    const float* Wqkv  = (const float*)d_in[1];
    const float* bqkv  = (const float*)d_in[2];
    const float* Wproj = (const float*)d_in[3];
    const float* bproj = (const float*)d_in[4];
    float* out = (float*)d_out;

    float *att_dev = nullptr, *wqkvt_dev = nullptr, *wprojt_dev = nullptr;
    cudaGetSymbolAddress((void**)&att_dev,    g_att);
    cudaGetSymbolAddress((void**)&wqkvt_dev,  g_wqkvt);
    cudaGetSymbolAddress((void**)&wprojt_dev, g_wprojt);

    // Transpose weights to K-major [N,K]
    {
        dim3 blk(32, 8);
        transpose_kernel<<<dim3(3 * D_ / 32, D_ / 32), blk>>>(Wqkv, wqkvt_dev, D_, 3 * D_);
        transpose_kernel<<<dim3(D_ / 32, D_ / 32), blk>>>(Wproj, wprojt_dev, D_, D_);
    }

    // QKV GEMM
    {
        dim3 grid(3 * D_ / 128, (B_ * S_) / 128);
        mma_gemm<3 * D_, 0><<<grid, 256>>>(x, wqkvt_dev, bqkv, nullptr);
    }

    // Attention (4 warps, 32x64 warp tile, register K/V prefetch)
    {
        const int smem = (128 + 64 + 64 + 128) * 68 * 4;  // 104,448
        cudaFuncSetAttribute(attn_mma, cudaFuncAttributeMaxDynamicSharedMemorySize, smem);
        dim3 grid(S_ / 128, H_, B_);
        attn_mma<<<grid, 128, smem>>>();
    }

    // Output projection
    {
        dim3 grid(D_ / 128, (B_ * S_) / 128);
        mma_gemm<D_, 1><<<grid, 256>>>(att_dev, wprojt_dev, bproj, out);
    }
}

// round 9
// speedup vs baseline: 2.5121x; 1.8618x over previous
#include <cuda_runtime.h>
#include <cuda_fp16.h>
#include <cstdint>

#define B_  2
#define S_  2048
#define D_  1024
#define H_  16
#define HD_ 64
#define SCALE_ 0.125f

// Scratch (half precision; 10-bit mantissa == tf32 mantissa)
__device__ __half g_q[(size_t)B_ * H_ * S_ * HD_];      // [b,h,s,hd]
__device__ __half g_k[(size_t)B_ * H_ * S_ * HD_];      // [b,h,s,hd]
__device__ __half g_v[(size_t)B_ * H_ * HD_ * S_];      // [b,h,hd,s]  (transposed!)
__device__ __half g_att[(size_t)B_ * S_ * D_];          // [b,s,D]
__device__ __half g_wqkvt[(size_t)3 * D_ * D_];         // Wqkv^T [3072,1024]
__device__ __half g_wprojt[(size_t)D_ * D_];            // Wproj^T [1024,1024]

__device__ __forceinline__ uint32_t packh2(float a, float b) {
    __half2 h = __floats2half2_rn(a, b);
    return *reinterpret_cast<uint32_t*>(&h);
}

// D = A(16x16 f16 row) * B(16x8 f16 col) + D, fp32 accum
__device__ __forceinline__ void mma16(float d[4], const uint32_t a[4], uint32_t b0, uint32_t b1) {
    asm volatile(
        "mma.sync.aligned.m16n8k16.row.col.f32.f16.f16.f32 "
        "{%0,%1,%2,%3},{%4,%5,%6,%7},{%8,%9},{%0,%1,%2,%3};"
        : "+f"(d[0]), "+f"(d[1]), "+f"(d[2]), "+f"(d[3])
        : "r"(a[0]), "r"(a[1]), "r"(a[2]), "r"(a[3]), "r"(b0), "r"(b1));
}

__device__ __forceinline__ void cp16(void* dst, const void* src) {
    uint32_t d = (uint32_t)__cvta_generic_to_shared(dst);
    asm volatile("cp.async.ca.shared.global [%0], [%1], 16;" :: "r"(d), "l"(src));
}
#define CP_COMMIT() asm volatile("cp.async.commit_group;" ::: "memory")
#define CP_WAIT1()  asm volatile("cp.async.wait_group 1;" ::: "memory")
#define CP_WAIT0()  asm volatile("cp.async.wait_group 0;" ::: "memory")

// ---------------------------------------------------------------------------
// Transpose: out[C,R] = half(in[R,C])
// ---------------------------------------------------------------------------
__global__ __launch_bounds__(256) void transpose_kernel(const float* __restrict__ in,
                                                        __half* __restrict__ out,
                                                        int R, int C) {
    __shared__ float t[32][33];
    const int bx = blockIdx.x * 32, by = blockIdx.y * 32;
    for (int i = threadIdx.y; i < 32; i += 8)
        t[i][threadIdx.x] = in[(size_t)(by + i) * C + bx + threadIdx.x];
    __syncthreads();
    for (int i = threadIdx.y; i < 32; i += 8)
        out[(size_t)(bx + i) * R + by + threadIdx.x] = __float2half(t[threadIdx.x][i]);
}

// ---------------------------------------------------------------------------
// fp16 mma GEMM: C[M,N] = A[M,1024] @ Bt[N,1024]^T + bias
// 128x128 CTA tile, 256 thr (8 warps 2x4), warp tile 64x32, BK=32.
// A fp32 (AH=false, cvt on store) or half (AH=true). B always half.
// MODE 0: scatter into g_q/g_k/g_v(half, V transposed); MODE 1: fp32 dense.
// ---------------------------------------------------------------------------
template <int NTOT, int MODE, bool AH>
__global__ __launch_bounds__(256) void mma_gemm_h(const void* __restrict__ Ap,
                                                  const __half* __restrict__ Bt,
                                                  const float* __restrict__ bias,
                                                  float* __restrict__ Cout) {
    constexpr int K = 1024;
    constexpr int ST = 20;               // 16 half2 words + 4 pad
    __shared__ uint32_t As[128 * ST];
    __shared__ uint32_t Bs[128 * ST];

    const int tid = threadIdx.x, lane = tid & 31, w = tid >> 5;
    const int bm = blockIdx.y * 128, bn = blockIdx.x * 128;
    const int wm = (w & 1) * 64, wn = (w >> 1) * 32;
    const int r = lane >> 2, c = lane & 3;

    float acc[4][4][4];
#pragma unroll
    for (int mi = 0; mi < 4; mi++)
#pragma unroll
        for (int ni = 0; ni < 4; ni++)
#pragma unroll
            for (int q = 0; q < 4; q++) acc[mi][ni][q] = 0.0f;

    for (int k0 = 0; k0 < K; k0 += 32) {
        if (AH) {
            const __half* Ah = (const __half*)Ap;
#pragma unroll
            for (int it = 0; it < 2; it++) {
                const int slot = tid + it * 256;
                const int row = slot >> 2, q = slot & 3;
                uint4 v = *reinterpret_cast<const uint4*>(Ah + (size_t)(bm + row) * K + k0 + q * 8);
                *reinterpret_cast<uint4*>(As + row * ST + q * 4) = v;
            }
        } else {
            const float* Af = (const float*)Ap;
#pragma unroll
            for (int it = 0; it < 4; it++) {
                const int slot = tid + it * 256;
                const int row = slot >> 3, c4 = slot & 7;
                float4 v = *reinterpret_cast<const float4*>(Af + (size_t)(bm + row) * K + k0 + c4 * 4);
                uint2 u = {packh2(v.x, v.y), packh2(v.z, v.w)};
                *reinterpret_cast<uint2*>(As + row * ST + c4 * 2) = u;
            }
        }
#pragma unroll
        for (int it = 0; it < 2; it++) {
            const int slot = tid + it * 256;
            const int row = slot >> 2, q = slot & 3;
            uint4 v = *reinterpret_cast<const uint4*>(Bt + (size_t)(bn + row) * K + k0 + q * 8);
            *reinterpret_cast<uint4*>(Bs + row * ST + q * 4) = v;
        }
        __syncthreads();

#pragma unroll
        for (int kg = 0; kg < 2; kg++) {
            const int kw = kg * 8;
            uint32_t af[4][4];
#pragma unroll
            for (int mi = 0; mi < 4; mi++) {
                af[mi][0] = As[(wm + mi * 16 + r) * ST + kw + c];
                af[mi][1] = As[(wm + mi * 16 + 8 + r) * ST + kw + c];
                af[mi][2] = As[(wm + mi * 16 + r) * ST + kw + c + 4];
                af[mi][3] = As[(wm + mi * 16 + 8 + r) * ST + kw + c + 4];
            }
            uint32_t bf[4][2];
#pragma unroll
            for (int ni = 0; ni < 4; ni++) {
                bf[ni][0] = Bs[(wn + ni * 8 + r) * ST + kw + c];
                bf[ni][1] = Bs[(wn + ni * 8 + r) * ST + kw + c + 4];
            }
#pragma unroll
            for (int mi = 0; mi < 4; mi++)
#pragma unroll
                for (int ni = 0; ni < 4; ni++)
                    mma16(acc[mi][ni], af[mi], bf[ni][0], bf[ni][1]);
        }
        __syncthreads();
    }

    // Epilogue
    const int c2 = (lane & 3) * 2;
#pragma unroll
    for (int mi = 0; mi < 4; mi++) {
#pragma unroll
        for (int ni = 0; ni < 4; ni++) {
            const int col = bn + wn + ni * 8 + c2;
            const float bi0 = bias[col], bi1 = bias[col + 1];
#pragma unroll
            for (int half_ = 0; half_ < 2; half_++) {
                const int row = bm + wm + mi * 16 + r + half_ * 8;
                const float v0 = acc[mi][ni][half_ * 2 + 0] + bi0;
                const float v1 = acc[mi][ni][half_ * 2 + 1] + bi1;
                if (MODE == 0) {
                    const int which = col >> 10;
                    const int d     = col & 1023;
                    const int h     = d >> 6;
                    const int hd    = d & 63;
                    const int b     = row >> 11;
                    const int s     = row & 2047;
                    if (which == 2) {
                        // V transposed: [b,h,hd,s]
                        const size_t base = (((size_t)b * H_ + h) * HD_) * S_;
                        g_v[base + (size_t)hd * S_ + s]       = __float2half(v0);
                        g_v[base + (size_t)(hd + 1) * S_ + s] = __float2half(v1);
                    } else {
                        const size_t dst = (((size_t)b * H_ + h) * S_ + s) * HD_ + hd;
                        __half2 hv = __floats2half2_rn(v0, v1);
                        if (which == 0) *reinterpret_cast<__half2*>(g_q + dst) = hv;
                        else            *reinterpret_cast<__half2*>(g_k + dst) = hv;
                    }
                } else {
                    float2 v = {v0, v1};
                    *reinterpret_cast<float2*>(Cout + (size_t)row * NTOT + col) = v;
                }
            }
        }
    }
}

// ---------------------------------------------------------------------------
// Flash attention, fp16 m16n8k16, register softmax + register-resident P.
// CTA: 128 thr (4 warps), Br=128, Bc=64, HD=64. Warp w owns rows [w*32,w*32+32).
// K/V stream via cp.async double-buffer; Q fragments hoisted to registers.
// SMEM (uint32 half2-words, stride 36): Qs[128][36], Ks/Vs 2 bufs [64][36].
// ---------------------------------------------------------------------------
__global__ __launch_bounds__(128, 2) void attn_h() {
    constexpr int ST = 36;   // 32 half2 words + 4 pad
    extern __shared__ uint32_t smu[];
    uint32_t* Qs = smu;                       // [128][36]
    uint32_t* Ks = Qs + 128 * ST;             // [2][64][36]
    uint32_t* Vs = Ks + 2 * 64 * ST;          // [2][64][36]  row=d, halves along s

    const int b  = blockIdx.z;
    const int h  = blockIdx.y;
    const int q0 = blockIdx.x * 128;

    const __half* Qg = g_q + (((size_t)b * H_ + h) * S_ + q0) * HD_;
    const __half* Kg = g_k + ((size_t)b * H_ + h) * S_ * HD_;
    const __half* Vg = g_v + ((size_t)b * H_ + h) * HD_ * S_;

    const int tid = threadIdx.x, lane = tid & 31, w = tid >> 5;
    const int wrow = w * 32;
    const int r = lane >> 2, c = lane & 3;
    const int c2 = c * 2;

    // issue tile loads (64 rows x 128B, 8 chunks/row; 4 chunks per thread)
    auto issue_k = [&](int kt, int buf) {
        uint32_t* Kb = Ks + buf * 64 * ST;
#pragma unroll
        for (int it = 0; it < 4; it++) {
            const int slot = tid + it * 128;
            const int row = slot >> 3, ch = slot & 7;
            cp16(Kb + row * ST + ch * 4, Kg + (size_t)(kt + row) * HD_ + ch * 8);
        }
    };
    auto issue_v = [&](int kt, int buf) {
        uint32_t* Vb = Vs + buf * 64 * ST;
#pragma unroll
        for (int it = 0; it < 4; it++) {
            const int slot = tid + it * 128;
            const int row = slot >> 3, ch = slot & 7;   // row = d
            cp16(Vb + row * ST + ch * 4, Vg + (size_t)row * S_ + kt + ch * 8);
        }
    };

    // Group 0: Q (128 rows x 8 chunks) + tile 0
#pragma unroll
    for (int it = 0; it < 8; it++) {
        const int slot = tid + it * 128;
        const int row = slot >> 3, ch = slot & 7;
        cp16(Qs + row * ST + ch * 4, Qg + (size_t)row * HD_ + ch * 8);
    }
    issue_k(0, 0); issue_v(0, 0);
    CP_COMMIT();
    // Group 1: tile 1
    issue_k(64, 1); issue_v(64, 1);
    CP_COMMIT();

    CP_WAIT1();          // group 0 (Q + tile0) done
    __syncthreads();

    // Hoist Q fragments (constant across k-loop)
    uint32_t qf[2][4][4];
#pragma unroll
    for (int mi = 0; mi < 2; mi++)
#pragma unroll
        for (int kg = 0; kg < 4; kg++) {
            const int kw = kg * 8;
            qf[mi][kg][0] = Qs[(wrow + mi * 16 + r) * ST + kw + c];
            qf[mi][kg][1] = Qs[(wrow + mi * 16 + 8 + r) * ST + kw + c];
            qf[mi][kg][2] = Qs[(wrow + mi * 16 + r) * ST + kw + c + 4];
            qf[mi][kg][3] = Qs[(wrow + mi * 16 + 8 + r) * ST + kw + c + 4];
        }

    float m[4], l[4];
#pragma unroll
    for (int i = 0; i < 4; i++) { m[i] = -1e30f; l[i] = 0.0f; }
    float O[2][8][4];
#pragma unroll
    for (int mi = 0; mi < 2; mi++)
#pragma unroll
        for (int ni = 0; ni < 8; ni++)
#pragma unroll
            for (int q = 0; q < 4; q++) O[mi][ni][q] = 0.0f;

    constexpr int NT = S_ / 64;   // 32 tiles
    for (int i = 0; i < NT; i++) {
        if (i < NT - 1) { CP_WAIT1(); } else { CP_WAIT0(); }
        __syncthreads();
        const int buf = i & 1;
        const uint32_t* Kb = Ks + buf * 64 * ST;
        const uint32_t* Vb = Vs + buf * 64 * ST;

        // S = Q @ K^T : 32 rows x 64 cols per warp
        float sf[2][8][4];
#pragma unroll
        for (int mi = 0; mi < 2; mi++)
#pragma unroll
            for (int ni = 0; ni < 8; ni++)
#pragma unroll
                for (int q = 0; q < 4; q++) sf[mi][ni][q] = 0.0f;
#pragma unroll
        for (int kg = 0; kg < 4; kg++) {
            const int kw = kg * 8;
#pragma unroll
            for (int ni = 0; ni < 8; ni++) {
                const uint32_t b0 = Kb[(ni * 8 + r) * ST + kw + c];
                const uint32_t b1 = Kb[(ni * 8 + r) * ST + kw + c + 4];
                mma16(sf[0][ni], qf[0][kg], b0, b1);
                mma16(sf[1][ni], qf[1][kg], b0, b1);
            }
        }

        // register softmax + pack P into A-fragments (all registers!)
        uint32_t pf[2][4][4];
#pragma unroll
        for (int mi = 0; mi < 2; mi++) {
            float mloc0 = -1e30f, mloc1 = -1e30f;
#pragma unroll
            for (int ni = 0; ni < 8; ni++) {
                sf[mi][ni][0] *= SCALE_; sf[mi][ni][1] *= SCALE_;
                sf[mi][ni][2] *= SCALE_; sf[mi][ni][3] *= SCALE_;
                mloc0 = fmaxf(mloc0, fmaxf(sf[mi][ni][0], sf[mi][ni][1]));
                mloc1 = fmaxf(mloc1, fmaxf(sf[mi][ni][2], sf[mi][ni][3]));
            }
            mloc0 = fmaxf(mloc0, __shfl_xor_sync(0xffffffffu, mloc0, 1));
            mloc0 = fmaxf(mloc0, __shfl_xor_sync(0xffffffffu, mloc0, 2));
            mloc1 = fmaxf(mloc1, __shfl_xor_sync(0xffffffffu, mloc1, 1));
            mloc1 = fmaxf(mloc1, __shfl_xor_sync(0xffffffffu, mloc1, 2));

            const float mnew0 = fmaxf(m[mi * 2 + 0], mloc0);
            const float mnew1 = fmaxf(m[mi * 2 + 1], mloc1);
            const float alpha0 = __expf(m[mi * 2 + 0] - mnew0);
            const float alpha1 = __expf(m[mi * 2 + 1] - mnew1);

            float ls0 = 0.0f, ls1 = 0.0f;
#pragma unroll
            for (int ni = 0; ni < 8; ni++) {
                const float p0 = __expf(sf[mi][ni][0] - mnew0);
                const float p1 = __expf(sf[mi][ni][1] - mnew0);
                const float p2 = __expf(sf[mi][ni][2] - mnew1);
                const float p3 = __expf(sf[mi][ni][3] - mnew1);
                ls0 += p0 + p1;
                ls1 += p2 + p3;
                sf[mi][ni][0] = p0; sf[mi][ni][1] = p1;
                sf[mi][ni][2] = p2; sf[mi][ni][3] = p3;
            }
            ls0 += __shfl_xor_sync(0xffffffffu, ls0, 1);
            ls0 += __shfl_xor_sync(0xffffffffu, ls0, 2);
            ls1 += __shfl_xor_sync(0xffffffffu, ls1, 1);
            ls1 += __shfl_xor_sync(0xffffffffu, ls1, 2);

            l[mi * 2 + 0] = l[mi * 2 + 0] * alpha0 + ls0;  m[mi * 2 + 0] = mnew0;
            l[mi * 2 + 1] = l[mi * 2 + 1] * alpha1 + ls1;  m[mi * 2 + 1] = mnew1;

#pragma unroll
            for (int ni = 0; ni < 8; ni++) {
                O[mi][ni][0] *= alpha0; O[mi][ni][1] *= alpha0;
                O[mi][ni][2] *= alpha1; O[mi][ni][3] *= alpha1;
            }
            // P accumulator -> fp16 A-fragment (pure register repack)
#pragma unroll
            for (int kg = 0; kg < 4; kg++) {
                pf[mi][kg][0] = packh2(sf[mi][2 * kg][0],     sf[mi][2 * kg][1]);
                pf[mi][kg][1] = packh2(sf[mi][2 * kg][2],     sf[mi][2 * kg][3]);
                pf[mi][kg][2] = packh2(sf[mi][2 * kg + 1][0], sf[mi][2 * kg + 1][1]);
                pf[mi][kg][3] = packh2(sf[mi][2 * kg + 1][2], sf[mi][2 * kg + 1][3]);
            }
        }

        // O += P @ V
#pragma unroll
        for (int kg = 0; kg < 4; kg++) {
            const int kw = kg * 8;
#pragma unroll
            for (int ni = 0; ni < 8; ni++) {
                const uint32_t b0 = Vb[(ni * 8 + r) * ST + kw + c];
                const uint32_t b1 = Vb[(ni * 8 + r) * ST + kw + c + 4];
                mma16(O[0][ni], pf[0][kg], b0, b1);
                mma16(O[1][ni], pf[1][kg], b0, b1);
            }
        }

        __syncthreads();   // done reading buf before refill
        if (i + 2 < NT) {
            issue_k((i + 2) * 64, buf);
            issue_v((i + 2) * 64, buf);
            CP_COMMIT();
        }
    }

    // Normalize and write out (half)
#pragma unroll
    for (int mi = 0; mi < 2; mi++) {
        const float il0 = 1.0f / l[mi * 2 + 0];
        const float il1 = 1.0f / l[mi * 2 + 1];
#pragma unroll
        for (int ni = 0; ni < 8; ni++) {
            const int col = h * HD_ + ni * 8 + c2;
            const int row0 = q0 + wrow + mi * 16 + r;
            __half2 v0 = __floats2half2_rn(O[mi][ni][0] * il0, O[mi][ni][1] * il0);
            __half2 v1 = __floats2half2_rn(O[mi][ni][2] * il1, O[mi][ni][3] * il1);
            *reinterpret_cast<__half2*>(g_att + ((size_t)b * S_ + row0) * D_ + col)     = v0;
            *reinterpret_cast<__half2*>(g_att + ((size_t)b * S_ + row0 + 8) * D_ + col) = v1;
        }
    }
}

// ---------------------------------------------------------------------------
extern "C" void kernel_launch(void* const* d_in, const int* in_sizes, int n_in,
                              void* d_out, int out_size) {
    (void)in_sizes; (void)n_in; (void)out_size;
    const float* x     = (const float*)d_in[0];
    const float* Wqkv  = (const float*)d_in[1];
    const float* bqkv  = (const float*)d_in[2];
    const float* Wproj = (const float*)d_in[3];
    const float* bproj = (const float*)d_in[4];
    float* out = (float*)d_out;

    __half *att_dev = nullptr, *wqkvt_dev = nullptr, *wprojt_dev = nullptr;
    cudaGetSymbolAddress((void**)&att_dev,    g_att);
    cudaGetSymbolAddress((void**)&wqkvt_dev,  g_wqkvt);
    cudaGetSymbolAddress((void**)&wprojt_dev, g_wprojt);

    // Transpose weights to K-major half [N,K]
    {
        dim3 blk(32, 8);
        transpose_kernel<<<dim3(3 * D_ / 32, D_ / 32), blk>>>(Wqkv, wqkvt_dev, D_, 3 * D_);
        transpose_kernel<<<dim3(D_ / 32, D_ / 32), blk>>>(Wproj, wprojt_dev, D_, D_);
    }

    // QKV GEMM (fp16 mma, A fp32->half on the fly)
    {
        dim3 grid(3 * D_ / 128, (B_ * S_) / 128);
        mma_gemm_h<3 * D_, 0, false><<<grid, 256>>>(x, wqkvt_dev, bqkv, nullptr);
    }

    // Attention (fp16 mma, cp.async double buffer, register P)
    {
        const int smem = (128 * 36 + 4 * 64 * 36) * 4;   // 55,296 B
        cudaFuncSetAttribute(attn_h, cudaFuncAttributeMaxDynamicSharedMemorySize, smem);
        dim3 grid(S_ / 128, H_, B_);
        attn_h<<<grid, 128, smem>>>();
    }

    // Output projection (fp16 mma, A half)
    {
        dim3 grid(D_ / 128, (B_ * S_) / 128);
        mma_gemm_h<D_, 1, true><<<grid, 256>>>(att_dev, wprojt_dev, bproj, out);
    }
}